// round 11
// baseline (speedup 1.0000x reference)
#include <cuda_runtime.h>
#include <cuda_bf16.h>
#include <cstdint>

// ---------------------------------------------------------------------------
// Edge2NodeFeatures via mma.sync (baseline-PTX HMMA, bf16 split x3 products):
//   h = LN(relu(A @ W + b)); out[n] = (scatter_add over src/dst of h) / deg
// Fused persistent kernel, 512 threads (16 warps), warp tile 16x64.
// ---------------------------------------------------------------------------

#define DEG_CAP (1 << 20)
__device__ float g_degree[DEG_CAP];
__device__ unsigned g_bar_count;
__device__ unsigned g_bar_sense;

#define SWZ128(b) ((b) ^ (((b) >> 3) & 0x70))

// ---------------- SMEM layout (dynamic) ----------------
#define OFF_W_HI 0          // 128 n-rows x 128B = 16384
#define OFF_W_LO 16384
#define OFF_A_HI 32768
#define OFF_A_LO 49152
#define OFF_SH   65536      // 128 rows x 528B   = 67584
#define OFF_PART 133120     // 128 rows x 2 x float2 = 2048
#define OFF_SRC  135168     // 128 x i32
#define OFF_DST  135680
#define OFF_PRM  136192     // bias,gamma,beta x 128 f32 = 1536
#define SMEM_TOTAL 137728

__device__ __forceinline__ uint32_t smem_u32(const void* p) {
    uint32_t a;
    asm("{ .reg .u64 t; cvta.to.shared.u64 t, %1; cvt.u32.u64 %0, t; }"
        : "=r"(a) : "l"(p));
    return a;
}

__device__ __forceinline__ void ldsm_x4(uint32_t addr, uint32_t& r0, uint32_t& r1,
                                        uint32_t& r2, uint32_t& r3) {
    asm volatile("ldmatrix.sync.aligned.m8n8.x4.shared.b16 {%0,%1,%2,%3}, [%4];"
                 : "=r"(r0), "=r"(r1), "=r"(r2), "=r"(r3) : "r"(addr));
}

__device__ __forceinline__ void mma16816(float* c,
                                         uint32_t a0, uint32_t a1, uint32_t a2, uint32_t a3,
                                         uint32_t b0, uint32_t b1) {
    asm volatile("mma.sync.aligned.m16n8k16.row.col.f32.bf16.bf16.f32 "
                 "{%0,%1,%2,%3}, {%4,%5,%6,%7}, {%8,%9}, {%0,%1,%2,%3};"
                 : "+f"(c[0]), "+f"(c[1]), "+f"(c[2]), "+f"(c[3])
                 : "r"(a0), "r"(a1), "r"(a2), "r"(a3), "r"(b0), "r"(b1));
}

__device__ __forceinline__ bool idx_is_64(const long long* eidx, int N) {
    bool ok = true;
#pragma unroll
    for (int t = 0; t < 4; t++)
        if ((unsigned long long)eidx[t] >= (unsigned long long)N) ok = false;
    return ok;
}

__global__ void zero_kernel(float4* out4, int n4, int N) {
    int i = blockIdx.x * blockDim.x + threadIdx.x;
    if (i < n4) out4[i] = make_float4(0.f, 0.f, 0.f, 0.f);
    if (i < N)  g_degree[i] = 0.f;
}

// ---------------------------------------------------------------------------
__global__ void __launch_bounds__(512, 1)
edge2node_fused(const float* __restrict__ edge_attr,
                const float* __restrict__ W,
                const float* __restrict__ bias,
                const float* __restrict__ gamma,
                const float* __restrict__ beta,
                const long long* __restrict__ eidx,
                float* __restrict__ out,
                int E, int ntiles, int Nn)
{
    extern __shared__ __align__(1024) char smem[];
    const uint32_t sa = smem_u32(smem);
    const int tid = threadIdx.x, wid = tid >> 5, lane = tid & 31;
    const int mw = wid & 7, nw = wid >> 3;     // 8 M-warps x 2 N-warps
    const int Mb = mw * 16, Nb = nw * 64;
    const bool is64 = idx_is_64(eidx, Nn);
    const int step = (int)gridDim.x;

    // ---- setup: W split hi/lo (SW128, [n][k]) + params table ----
    for (int idx = tid; idx < 64 * 128; idx += 512) {
        int k = idx >> 7, n = idx & 127;
        float w = W[idx];
        __nv_bfloat16 hi = __float2bfloat16(w);
        float lo = w - __bfloat162float(hi);
        uint32_t sw = SWZ128((uint32_t)(n * 128 + k * 2));
        *(unsigned short*)(smem + OFF_W_HI + sw) = __bfloat16_as_ushort(hi);
        *(unsigned short*)(smem + OFF_W_LO + sw) = __bfloat16_as_ushort(__float2bfloat16(lo));
    }
    if (tid < 128) {
        ((float*)(smem + OFF_PRM))[tid]        = bias[tid];
        ((float*)(smem + OFF_PRM + 512))[tid]  = gamma[tid];
        ((float*)(smem + OFF_PRM + 1024))[tid] = beta[tid];
    }

    // ldmatrix lane row-offsets (bytes, pre-swizzle)
    const int grp = lane >> 3, r8 = lane & 7;
    const uint32_t rowoff_a =
        (uint32_t)((Mb + (grp & 1) * 8 + r8) * 128 + (grp >> 1) * 16);
    uint32_t rowoff_b[4];
#pragma unroll
    for (int bt = 0; bt < 4; bt++)
        rowoff_b[bt] = (uint32_t)((Nb + bt * 16 + (grp >> 1) * 8 + r8) * 128 + (grp & 1) * 16);

    // ---- prefetch first tile ----
    float4 pref[4];
    int ps = 0, pd = 0;
    int tile = blockIdx.x;
    if (tile < ntiles) {
        const float4* Ap = (const float4*)edge_attr + (size_t)tile * 128 * 16;
#pragma unroll
        for (int u = 0; u < 4; u++) {
            int idx = tid + u * 512, row = idx >> 4;
            pref[u] = (tile * 128 + row < E) ? Ap[idx] : make_float4(0.f, 0.f, 0.f, 0.f);
        }
        if (tid < 128 && tile * 128 + tid < E) {
            int e = tile * 128 + tid;
            ps = is64 ? (int)eidx[e] : ((const int*)eidx)[e];
            pd = is64 ? (int)eidx[(size_t)E + e] : ((const int*)eidx)[(size_t)E + e];
        }
    }
    __syncthreads();

    // =======================  main loop  =======================
    while (tile < ntiles) {
        const int base_e = tile * 128;

        // ---- store staged A (split bf16 hi/lo, SW128) + indices + degree ----
#pragma unroll
        for (int u = 0; u < 4; u++) {
            int idx = tid + u * 512, row = idx >> 4, c4 = idx & 15;
            float4 a = pref[u];
            __nv_bfloat16 h0 = __float2bfloat16(a.x), h1 = __float2bfloat16(a.y);
            __nv_bfloat16 h2 = __float2bfloat16(a.z), h3 = __float2bfloat16(a.w);
            float l0 = a.x - __bfloat162float(h0), l1 = a.y - __bfloat162float(h1);
            float l2 = a.z - __bfloat162float(h2), l3 = a.w - __bfloat162float(h3);
            uint32_t hi01 = ((uint32_t)__bfloat16_as_ushort(h1) << 16) | __bfloat16_as_ushort(h0);
            uint32_t hi23 = ((uint32_t)__bfloat16_as_ushort(h3) << 16) | __bfloat16_as_ushort(h2);
            uint32_t lo01 = ((uint32_t)__bfloat16_as_ushort(__float2bfloat16(l1)) << 16)
                          | __bfloat16_as_ushort(__float2bfloat16(l0));
            uint32_t lo23 = ((uint32_t)__bfloat16_as_ushort(__float2bfloat16(l3)) << 16)
                          | __bfloat16_as_ushort(__float2bfloat16(l2));
            uint32_t sw = SWZ128((uint32_t)(row * 128 + c4 * 8));
            *(uint2*)(smem + OFF_A_HI + sw) = make_uint2(hi01, hi23);
            *(uint2*)(smem + OFF_A_LO + sw) = make_uint2(lo01, lo23);
        }
        if (tid < 128) {
            ((int*)(smem + OFF_SRC))[tid] = ps;
            ((int*)(smem + OFF_DST))[tid] = pd;
            if (base_e + tid < E) {
                atomicAdd(&g_degree[ps], 1.0f);
                atomicAdd(&g_degree[pd], 1.0f);
            }
        }
        __syncthreads();   // S1

        // ---- prefetch next tile (hidden under GEMM) ----
        const int next = tile + step;
        if (next < ntiles) {
            const float4* Ap = (const float4*)edge_attr + (size_t)next * 128 * 16;
#pragma unroll
            for (int u = 0; u < 4; u++) {
                int idx = tid + u * 512, row = idx >> 4;
                pref[u] = (next * 128 + row < E) ? Ap[idx] : make_float4(0.f, 0.f, 0.f, 0.f);
            }
            if (tid < 128 && next * 128 + tid < E) {
                int e = next * 128 + tid;
                ps = is64 ? (int)eidx[e] : ((const int*)eidx)[e];
                pd = is64 ? (int)eidx[(size_t)E + e] : ((const int*)eidx)[(size_t)E + e];
            }
        }

        // ---- GEMM: c = bias; c += Ahi@Whi + Ahi@Wlo + Alo@Whi ----
        float c[8][4];
#pragma unroll
        for (int ni = 0; ni < 8; ni++) {
            float2 b2 = *(const float2*)(smem + OFF_PRM + (Nb + ni * 8 + (lane & 3) * 2) * 4);
#pragma unroll
            for (int rr = 0; rr < 4; rr++)
                c[ni][rr] = (rr & 1) ? b2.y : b2.x;
        }

#pragma unroll
        for (int ks = 0; ks < 4; ks++) {
            uint32_t aH[4], aL[4], bH[4][4], bL[4][4];
            ldsm_x4(sa + OFF_A_HI + SWZ128(rowoff_a + ks * 32), aH[0], aH[1], aH[2], aH[3]);
            ldsm_x4(sa + OFF_A_LO + SWZ128(rowoff_a + ks * 32), aL[0], aL[1], aL[2], aL[3]);
#pragma unroll
            for (int bt = 0; bt < 4; bt++) {
                ldsm_x4(sa + OFF_W_HI + SWZ128(rowoff_b[bt] + ks * 32),
                        bH[bt][0], bH[bt][1], bH[bt][2], bH[bt][3]);
                ldsm_x4(sa + OFF_W_LO + SWZ128(rowoff_b[bt] + ks * 32),
                        bL[bt][0], bL[bt][1], bL[bt][2], bL[bt][3]);
            }
#pragma unroll
            for (int ni = 0; ni < 8; ni++) {
                const int bt = ni >> 1, h = (ni & 1) * 2;
                mma16816(c[ni], aH[0], aH[1], aH[2], aH[3], bH[bt][h], bH[bt][h + 1]);
                mma16816(c[ni], aH[0], aH[1], aH[2], aH[3], bL[bt][h], bL[bt][h + 1]);
                mma16816(c[ni], aL[0], aL[1], aL[2], aL[3], bH[bt][h], bH[bt][h + 1]);
            }
        }

        // ---- relu + per-row stats (2 rows/thread) ----
        float sm[2] = {0.f, 0.f}, sq[2] = {0.f, 0.f};
#pragma unroll
        for (int ni = 0; ni < 8; ni++)
#pragma unroll
            for (int rr = 0; rr < 4; rr++) {
                float h = fmaxf(c[ni][rr], 0.f);
                c[ni][rr] = h;
                int slot = rr >> 1;
                sm[slot] += h;
                sq[slot] = fmaf(h, h, sq[slot]);
            }
#pragma unroll
        for (int slot = 0; slot < 2; slot++) {
            sm[slot] += __shfl_xor_sync(0xffffffffu, sm[slot], 1);
            sq[slot] += __shfl_xor_sync(0xffffffffu, sq[slot], 1);
            sm[slot] += __shfl_xor_sync(0xffffffffu, sm[slot], 2);
            sq[slot] += __shfl_xor_sync(0xffffffffu, sq[slot], 2);
        }
        if ((lane & 3) == 0) {
#pragma unroll
            for (int slot = 0; slot < 2; slot++) {
                int row = Mb + slot * 8 + (lane >> 2);
                *(float2*)(smem + OFF_PART + (row * 2 + nw) * 8) = make_float2(sm[slot], sq[slot]);
            }
        }
        __syncthreads();   // S2

        // ---- normalize + stage ----
        float mu[2], rs[2];
#pragma unroll
        for (int slot = 0; slot < 2; slot++) {
            int row = Mb + slot * 8 + (lane >> 2);
            float2 p0 = *(const float2*)(smem + OFF_PART + (row * 2 + 0) * 8);
            float2 p1 = *(const float2*)(smem + OFF_PART + (row * 2 + 1) * 8);
            float sum = p0.x + p1.x, ss = p0.y + p1.y;
            mu[slot] = sum * (1.0f / 128.0f);
            float var = ss * (1.0f / 128.0f) - mu[slot] * mu[slot];
            rs[slot] = rsqrtf(var + 1e-5f);
        }
#pragma unroll
        for (int rh = 0; rh < 2; rh++) {
            int row = Mb + rh * 8 + (lane >> 2);
            char* rp = smem + OFF_SH + row * 528;
#pragma unroll
            for (int ni = 0; ni < 8; ni++) {
                int cb = (Nb + ni * 8 + (lane & 3) * 2) * 4;
                float2 gg = *(const float2*)(smem + OFF_PRM + 512 + cb);
                float2 tt = *(const float2*)(smem + OFF_PRM + 1024 + cb);
                float y0 = (c[ni][rh * 2 + 0] - mu[rh]) * rs[rh] * gg.x + tt.x;
                float y1 = (c[ni][rh * 2 + 1] - mu[rh]) * rs[rh] * gg.y + tt.y;
                *(float2*)(rp + cb) = make_float2(y0, y1);
            }
        }
        __syncthreads();   // S3

        // ---- scatter: 2 endpoints x 128 edges x 32 quads, coalesced red.v4 ----
#pragma unroll 8
        for (int r2 = 0; r2 < 16; r2++) {
            int item = tid + 512 * r2;
            int q = item & 31;
            int rowsel = item >> 5;
            int ep = rowsel >> 7, m = rowsel & 127;
            if (base_e + m < E) {
                int node = ((const int*)(smem + (ep ? OFF_DST : OFF_SRC)))[m];
                float4 v = *(const float4*)(smem + OFF_SH + m * 528 + q * 16);
                float* p = out + (size_t)node * 128 + q * 4;
                asm volatile("red.global.add.v4.f32 [%0], {%1,%2,%3,%4};"
                             :: "l"(p), "f"(v.x), "f"(v.y), "f"(v.z), "f"(v.w)
                             : "memory");
            }
        }
        __syncthreads();   // S4
        tile = next;
    }

    // ======================= grid barrier =======================
    __threadfence();
    __syncthreads();
    if (tid == 0) {
        unsigned s = atomicAdd(&g_bar_sense, 0u);
        unsigned prev = atomicAdd(&g_bar_count, 1u);
        if (prev == gridDim.x - 1) {
            atomicExch(&g_bar_count, 0u);
            atomicExch(&g_bar_sense, s ^ 1u);
        } else {
            while (atomicAdd(&g_bar_sense, 0u) == s) { __nanosleep(64); }
        }
    }
    __syncthreads();
    __threadfence();

    // ======================= finalize =======================
    {
        const int n4 = Nn * 32;
        float4* out4 = (float4*)out;
        for (int i = blockIdx.x * 512 + tid; i < n4; i += step * 512) {
            int row = i >> 5;
            float inv = 1.0f / fmaxf(g_degree[row], 1.0f);
            float4 v = out4[i];
            v.x *= inv; v.y *= inv; v.z *= inv; v.w *= inv;
            out4[i] = v;
        }
    }
}

extern "C" void kernel_launch(void* const* d_in, const int* in_sizes, int n_in,
                              void* d_out, int out_size) {
    const float* edge_attr = (const float*)d_in[0];
    const float* W         = (const float*)d_in[1];
    const float* b         = (const float*)d_in[2];
    const float* gamma     = (const float*)d_in[3];
    const float* beta      = (const float*)d_in[4];
    const long long* eidx  = (const long long*)d_in[5];
    float* out = (float*)d_out;

    const int E  = in_sizes[0] / 64;
    const int N  = out_size / 128;
    const int n4 = out_size / 4;

    static int nsm = 0;
    if (nsm == 0) {
        cudaDeviceGetAttribute(&nsm, cudaDevAttrMultiProcessorCount, 0);
        if (nsm <= 0) nsm = 148;
        cudaFuncSetAttribute(edge2node_fused,
                             cudaFuncAttributeMaxDynamicSharedMemorySize, SMEM_TOTAL);
    }

    zero_kernel<<<(n4 + 255) / 256, 256>>>((float4*)out, n4, N);

    const int ntiles = (E + 127) / 128;
    edge2node_fused<<<nsm, 512, SMEM_TOTAL>>>(edge_attr, W, b, gamma, beta, eidx,
                                              out, E, ntiles, N);
}